// round 7
// baseline (speedup 1.0000x reference)
#include <cuda_runtime.h>
#include <cstdint>
#include <climits>

// ---------------- problem constants (match reference exactly) ----------------
#define BB   4
#define NPTS 300000
#define NC   5
#define GXX  432
#define GYY  496
#define GZZ  1
#define NVOX (GXX * GYY * GZZ)          // 214272
#define MAXV 40000
#define MAXP 30
#define CAP  48                          // per-voxel index bucket capacity
#define CHUNK 1024
#define NB   ((NVOX + CHUNK - 1) / CHUNK)   // 210

#define FEATS_ELEMS ((size_t)BB * MAXV * MAXP * NC)   // 24,000,000 floats
#define F4_FEATS (24000000 / 4)          // 6,000,000 float4
#define F4_COORD ((BB * MAXV * 4) / 4)   // 160,000 float4

#define I4_CELL  ((BB * NVOX) / 2)       // g_cell (int2) viewed as int4
#define I4_AGG   ((BB * NB + 3) / 4)
#define FILL_TOTAL (I4_CELL + I4_AGG + F4_COORD)

#define VALIDF (1 << 30)
#define ROWF   (MAXP * NC)               // 150 floats per feats row

// ---------------- static device scratch ----------------------------------------
__device__ int2 g_cell  [BB * NVOX];     // .x = count, .y = rank
__device__ int4 g_agg4  [I4_AGG];
__device__ int  g_bucket[(size_t)BB * NVOX * CAP];

#define G_AGG ((int*)g_agg4)

// ---------------- side-stream: zero the 96MB feats region ----------------------
__global__ void k_zero(float4* __restrict__ feats4) {
    int tid = blockIdx.x * blockDim.x + threadIdx.x;
    int nthreads = gridDim.x * blockDim.x;
    const float4 z4 = make_float4(0.f, 0.f, 0.f, 0.f);
    for (int i = tid; i < F4_FEATS; i += nthreads) feats4[i] = z4;
}

// ---------------- init: cell {0,0}, agg 0, coords -1 ---------------------------
__global__ void k_fill(float4* __restrict__ out4) {
    int i = blockIdx.x * blockDim.x + threadIdx.x;
    if (i < I4_CELL) { ((int4*)g_cell)[i] = make_int4(0, 0, 0, 0); return; }
    i -= I4_CELL;
    if (i < I4_AGG) { g_agg4[i] = make_int4(0, 0, 0, 0); return; }
    i -= I4_AGG;
    if (i < F4_COORD) out4[F4_FEATS + i] = make_float4(-1.f, -1.f, -1.f, -1.f);
}

// ---------------- pass 1: voxelize + bucket append ----------------------------
__global__ void k_points(const float* __restrict__ pts) {
    int tid = blockIdx.x * blockDim.x + threadIdx.x;
    if (tid >= BB * NPTS) return;
    int b = tid / NPTS;
    int n = tid - b * NPTS;
    const float* p = pts + (size_t)tid * NC;
    float x = __ldg(p + 0), y = __ldg(p + 1), z = __ldg(p + 2);
    // identical float32 ops as reference: floor((p - lo) / vs)
    int ix = (int)floorf((x - 0.0f)   / 0.16f);
    int iy = (int)floorf((y + 39.68f) / 0.16f);
    int iz = (int)floorf((z + 3.0f)   / 4.0f);
    if (ix < 0 || ix >= GXX || iy < 0 || iy >= GYY || iz < 0 || iz >= GZZ) return;
    int vid = (iz * GYY + iy) * GXX + ix;
    int cell = b * NVOX + vid;
    int pos = atomicAdd(&g_cell[cell].x, 1);
    if (pos < CAP) g_bucket[(size_t)cell * CAP + pos] = n;
}

// ---------------- single-pass scan with decoupled lookback --------------------
// 840 blocks (256 thr) all fit in one wave on 148 SMs -> spin-wait is safe.
// Writes per-cell rank (g_cell[].y) AND the coords rows (coords = f(vid, rank)).
__global__ void k_scan(float* __restrict__ out) {
    int blk = blockIdx.x;
    int b  = blk / NB;
    int cb = blk - b * NB;
    int t  = threadIdx.x;
    __shared__ int sh[256];

    const int2* cnt = g_cell + b * NVOX;
    int base = cb * CHUNK + t * 4;
    int f0 = 0, f1 = 0, f2 = 0, f3 = 0;
    if (base + 0 < NVOX) f0 = (cnt[base + 0].x > 0);
    if (base + 1 < NVOX) f1 = (cnt[base + 1].x > 0);
    if (base + 2 < NVOX) f2 = (cnt[base + 2].x > 0);
    if (base + 3 < NVOX) f3 = (cnt[base + 3].x > 0);
    int s = f0 + f1 + f2 + f3;
    sh[t] = s;
    __syncthreads();
    #pragma unroll
    for (int off = 1; off < 256; off <<= 1) {   // Hillis–Steele inclusive
        int v = (t >= off) ? sh[t - off] : 0;
        __syncthreads();
        sh[t] += v;
        __syncthreads();
    }
    int excl  = sh[t] - s;
    int total = sh[255];

    // publish this chunk's aggregate ASAP
    if (t == 0) atomicExch(&G_AGG[blk], total | VALIDF);

    // lookback: sum all predecessor aggregates (within this batch)
    int partial = 0;
    for (int j = t; j < cb; j += 256) {
        int v;
        do { v = atomicAdd(&G_AGG[b * NB + j], 0); } while (!(v & VALIDF));
        partial += (v & (VALIDF - 1));
    }
    __syncthreads();
    sh[t] = partial;
    __syncthreads();
    #pragma unroll
    for (int off = 128; off > 0; off >>= 1) {
        if (t < off) sh[t] += sh[t + off];
        __syncthreads();
    }
    int r = sh[0] + excl;

    float4* coords = (float4*)(out + FEATS_ELEMS);
    #pragma unroll
    for (int q = 0; q < 4; q++) {
        int f = (q == 0) ? f0 : (q == 1) ? f1 : (q == 2) ? f2 : f3;
        if (f) {
            int vid = base + q;
            g_cell[b * NVOX + vid].y = r;
            if (r < MAXV) {
                int izc = vid / (GXX * GYY);
                int rem = vid - izc * (GXX * GYY);
                coords[b * MAXV + r] = make_float4((float)b, (float)izc,
                                                   (float)(rem / GXX),
                                                   (float)(rem % GXX));
            }
            r++;
        }
    }
}

// ---------------- scatter: one thread per point --------------------------------
// int2 cell-info load and first-4 bucket loads issue concurrently (independent
// addresses) -> 1 L2 round-trip on the critical path instead of 3.
__global__ void k_scatter(const float* __restrict__ pts, float* __restrict__ out) {
    int tid = blockIdx.x * blockDim.x + threadIdx.x;
    if (tid >= BB * NPTS) return;
    int b = tid / NPTS;
    int n = tid - b * NPTS;
    const float* p = pts + (size_t)tid * NC;
    float x = __ldg(p + 0), y = __ldg(p + 1), z = __ldg(p + 2);
    int ix = (int)floorf((x - 0.0f)   / 0.16f);
    int iy = (int)floorf((y + 39.68f) / 0.16f);
    int iz = (int)floorf((z + 3.0f)   / 4.0f);
    if (ix < 0 || ix >= GXX || iy < 0 || iy >= GYY || iz < 0 || iz >= GZZ) return;
    int vid = (iz * GYY + iy) * GXX + ix;
    int cell = b * NVOX + vid;

    const int* bk = g_bucket + (size_t)cell * CAP;
    int2 ci = __ldg(&g_cell[cell]);           // {count, rank}
    int e0 = __ldg(bk + 0);                   // prefetch in parallel with ci
    int e1 = __ldg(bk + 1);
    int e2 = __ldg(bk + 2);
    int e3 = __ldg(bk + 3);

    if (ci.y >= MAXV) return;                 // voxel beyond unique cap
    int m = ci.x < CAP ? ci.x : CAP;

    int r = 0;
    bool found = false;
    if (m > 0) { r += (e0 < n); found |= (e0 == n); }
    if (m > 1) { r += (e1 < n); found |= (e1 == n); }
    if (m > 2) { r += (e2 < n); found |= (e2 == n); }
    if (m > 3) { r += (e3 < n); found |= (e3 == n); }
    for (int j = 4; j < m; j++) {
        int e = __ldg(bk + j);
        r += (e < n);
        found |= (e == n);
    }
    if (!found || r >= MAXP) return;          // overflow-dropped or beyond 30

    float* fo = out + ((size_t)(b * MAXV + ci.y)) * ROWF + r * NC;
    fo[0] = (x - 0.0f)   / 69.12f;
    fo[1] = (y + 39.68f) / 79.36f;
    fo[2] = (z + 3.0f)   / 4.0f;
    fo[3] = __ldg(p + 3);
    fo[4] = __ldg(p + 4);
}

// ---------------- launch: forked graph ------------------------------------------
//   main:  fill -> points -> scan ----------\
//   side:  zero (96MB feats) ---------------+--> scatter
extern "C" void kernel_launch(void* const* d_in, const int* in_sizes, int n_in,
                              void* d_out, int out_size) {
    const float* pts = (const float*)d_in[0];
    float* out = (float*)d_out;

    cudaStream_t side;
    cudaEvent_t eFork, eJoin;
    cudaStreamCreateWithFlags(&side, cudaStreamNonBlocking);
    cudaEventCreateWithFlags(&eFork, cudaEventDisableTiming);
    cudaEventCreateWithFlags(&eJoin, cudaEventDisableTiming);

    // fork: side stream zeroes the feats region concurrently
    cudaEventRecord(eFork, 0);
    cudaStreamWaitEvent(side, eFork, 0);
    k_zero<<<2048, 256, 0, side>>>((float4*)out);
    cudaEventRecord(eJoin, side);

    // main chain
    k_fill  <<<(FILL_TOTAL + 255) / 256, 256>>>((float4*)out);
    k_points<<<(BB * NPTS + 255) / 256, 256>>>(pts);
    k_scan  <<<BB * NB, 256>>>(out);

    // join: scatter writes into the zeroed feats region
    cudaStreamWaitEvent(0, eJoin, 0);
    k_scatter<<<(BB * NPTS + 255) / 256, 256>>>(pts, out);

    // NOTE: side/eFork/eJoin intentionally not destroyed here — destroying
    // objects referenced by an in-progress capture is invalid; kernel_launch
    // is only invoked a handful of times (host-side objects, no device memory).
}